// round 9
// baseline (speedup 1.0000x reference)
#include <cuda_runtime.h>
#include <cstddef>

#define NUQ 500000
#define NIQ 100000
#define FDIM 300
#define DQ 64
#define NE 2000000
#define NL 1000000
#define NTOT (NUQ + NIQ)      // 600000
#define NADJ (2 * NE)         // 4000000
#define NBLK 293              // ceil(NTOT / 2048)

typedef unsigned long long u64;

// ---------------- device scratch (no runtime allocation allowed) ----------------
__device__ __align__(16) float g_xu[(size_t)NUQ * DQ];     // user features (in-place per layer)
__device__ __align__(16) float g_xi[(size_t)NIQ * DQ];     // item features (in-place per layer)
__device__ __align__(16) float g_agg_u[(size_t)NUQ * DQ];  // mean of item msgs at users
__device__ __align__(16) float g_agg_i[(size_t)NIQ * DQ];  // mean of user msgs at items
__device__ int g_cnt[NTOT];       // degrees: users [0,NU), items [NU,NU+NI)
__device__ int g_off[NTOT];       // exclusive scan of g_cnt
__device__ int g_cur[NTOT];       // fill cursors
__device__ int g_adj[NADJ];       // user buckets hold item ids; item buckets hold user ids
__device__ int g_bsum[NBLK];

// ---------------- helpers ----------------
__device__ __forceinline__ void fma2(u64& acc, u64 a, u64 b) {
    asm("fma.rn.f32x2 %0, %1, %2, %0;" : "+l"(acc) : "l"(a), "l"(b));
}
__device__ __forceinline__ u64 pack2(float x, float y) {
    u64 r; asm("mov.b64 %0, {%1, %2};" : "=l"(r) : "f"(x), "f"(y)); return r;
}
__device__ __forceinline__ float2 unpack2(u64 v) {
    float2 r; asm("mov.b64 {%0, %1}, %2;" : "=f"(r.x), "=f"(r.y) : "l"(v)); return r;
}
__device__ __forceinline__ int clampi(int v, int lo, int hi) {
    return min(max(v, lo), hi);
}
__device__ __forceinline__ int warp_incl_scan(int v) {
    int lane = threadIdx.x & 31;
#pragma unroll
    for (int d = 1; d < 32; d <<= 1) {
        int n = __shfl_up_sync(0xffffffffu, v, d);
        if (lane >= d) v += n;
    }
    return v;
}

// ---------------- CSR build ----------------
__global__ void k_zero_cnt() {
    for (int i = blockIdx.x * blockDim.x + threadIdx.x; i < NTOT;
         i += gridDim.x * blockDim.x) g_cnt[i] = 0;
}

__global__ void k_count(const int* __restrict__ esrc, const int* __restrict__ edst) {
    int e = blockIdx.x * blockDim.x + threadIdx.x;
    if (e >= NE) return;
    int u  = clampi(esrc[e], 0, NUQ - 1);
    int it = clampi(edst[e], 0, NIQ - 1);
    atomicAdd(&g_cnt[u], 1);
    atomicAdd(&g_cnt[NUQ + it], 1);
}

// 3-phase exclusive scan of g_cnt -> g_off (chunk = 2048 per block)
__global__ void __launch_bounds__(1024) k_scan1() {
    __shared__ int wsum[32];
    int t = threadIdx.x, lane = t & 31, w = t >> 5;
    int i0 = blockIdx.x * 2048 + 2 * t;
    int a = (i0 < NTOT)     ? g_cnt[i0]     : 0;
    int b = (i0 + 1 < NTOT) ? g_cnt[i0 + 1] : 0;
    int s = a + b;
    int incl = warp_incl_scan(s);
    if (lane == 31) wsum[w] = incl;
    __syncthreads();
    if (w == 0) {
        int ws = wsum[lane];
        int wincl = warp_incl_scan(ws);
        wsum[lane] = wincl - ws;                       // exclusive warp offset
        if (lane == 31) g_bsum[blockIdx.x] = wincl;    // block total
    }
    __syncthreads();
    int excl = incl - s + wsum[w];
    if (i0 < NTOT)     g_off[i0]     = excl;
    if (i0 + 1 < NTOT) g_off[i0 + 1] = excl + a;
}

__global__ void __launch_bounds__(512) k_scan2() {   // scans NBLK(<=512) block sums
    __shared__ int wsum[16];
    int t = threadIdx.x, lane = t & 31, w = t >> 5;
    int v0 = (t < NBLK) ? g_bsum[t] : 0;
    int incl = warp_incl_scan(v0);
    if (lane == 31) wsum[w] = incl;
    __syncthreads();
    if (w == 0 && lane < 16) {
        int ws = wsum[lane];
        int wincl = ws;
#pragma unroll
        for (int d = 1; d < 16; d <<= 1) {
            int n = __shfl_up_sync(0x0000ffffu, wincl, d, 16);
            if (lane >= d) wincl += n;
        }
        wsum[lane] = wincl - ws;
    }
    __syncthreads();
    if (t < NBLK) g_bsum[t] = incl - v0 + wsum[w];
}

__global__ void __launch_bounds__(1024) k_scan3() {
    int add = g_bsum[blockIdx.x];
    int i = blockIdx.x * 2048 + threadIdx.x;
#pragma unroll
    for (int r = 0; r < 2; r++, i += 1024) {
        if (i < NTOT) { int o = g_off[i] + add; g_off[i] = o; g_cur[i] = o; }
    }
}

__global__ void k_fill(const int* __restrict__ esrc, const int* __restrict__ edst) {
    int e = blockIdx.x * blockDim.x + threadIdx.x;
    if (e >= NE) return;
    int u  = clampi(esrc[e], 0, NUQ - 1);
    int it = clampi(edst[e], 0, NIQ - 1);
    int p1 = clampi(atomicAdd(&g_cur[u], 1),        0, NADJ - 1);
    int p2 = clampi(atomicAdd(&g_cur[NUQ + it], 1), 0, NADJ - 1);
    g_adj[p1] = it;   // user bucket: neighbor item ids
    g_adj[p2] = u;    // item bucket: neighbor user ids
}

// ---------------- input layers ----------------
// x_user = user_emb_w[user_node_id]  (faithful gather; one float4 per thread)
__global__ void k_gather_user(const float4* __restrict__ emb, const int* __restrict__ uid) {
    size_t i = blockIdx.x * (size_t)blockDim.x + threadIdx.x;  // over NUQ*16 float4s
    int row = (int)(i >> 4);
    int c = (int)(i & 15);
    int id = clampi(uid[row], 0, NUQ - 1);
    ((float4*)g_xu)[i] = emb[(size_t)id * 16 + c];
}

// g_xi = item_x @ W + b. Warp computes 4 rows; W staged in shared in
// k-pair-interleaved layout so each fma.rn.f32x2 consumes a packed x pair.
__global__ void __launch_bounds__(256) k_itemlin(const float* __restrict__ x,
                                                 const float* __restrict__ W,
                                                 const float* __restrict__ b) {
    __shared__ __align__(16) float ws[75 * 128];  // 150 k's per chunk: 75 pairs x 64 d x 2
    int tid = threadIdx.x, lane = tid & 31, warp = tid >> 5;
    int row0 = (blockIdx.x * 8 + warp) * 4;

    u64 acc[4][2];
#pragma unroll
    for (int r = 0; r < 4; r++) { acc[r][0] = 0ull; acc[r][1] = 0ull; }

    for (int chunk = 0; chunk < 2; chunk++) {
        if (chunk) __syncthreads();
        for (int idx = tid; idx < 75 * 64; idx += 256) {
            int p = idx >> 6, d = idx & 63;
            int k = chunk * 150 + 2 * p;
            *(float2*)&ws[p * 128 + 2 * d] = make_float2(W[k * 64 + d], W[(k + 1) * 64 + d]);
        }
        __syncthreads();
        const float* xb = x + (size_t)row0 * FDIM + chunk * 150;
        for (int p = 0; p < 75; p++) {
            u64 w0 = *(const u64*)&ws[p * 128 + 2 * lane];
            u64 w1 = *(const u64*)&ws[p * 128 + 2 * lane + 64];
#pragma unroll
            for (int r = 0; r < 4; r++) {
                float2 xf = *(const float2*)(xb + (size_t)r * FDIM + 2 * p);
                u64 xv = pack2(xf.x, xf.y);
                fma2(acc[r][0], xv, w0);
                fma2(acc[r][1], xv, w1);
            }
        }
    }
    float b0 = b[lane], b1 = b[lane + 32];
#pragma unroll
    for (int r = 0; r < 4; r++) {
        float2 a0 = unpack2(acc[r][0]), a1 = unpack2(acc[r][1]);
        g_xi[(size_t)(row0 + r) * DQ + lane]      = b0 + a0.x + a0.y;
        g_xi[(size_t)(row0 + r) * DQ + lane + 32] = b1 + a1.x + a1.y;
    }
}

// ---------------- aggregation (gather over CSR): agg = mean of neighbor rows --
template <bool USER>
__global__ void __launch_bounds__(256) k_agg() {
    int gw = (blockIdx.x * blockDim.x + threadIdx.x) >> 5;
    int lane = threadIdx.x & 31;
    int nwarp = (gridDim.x * blockDim.x) >> 5;
    const int n = USER ? NUQ : NIQ;
    const float* __restrict__ src = USER ? g_xi : g_xu;
    float* __restrict__ dst       = USER ? g_agg_u : g_agg_i;

    for (int node = gw; node < n; node += nwarp) {
        int key = USER ? node : NUQ + node;
        int start = g_off[key];
        int len = g_cnt[key];
        float2 acc = make_float2(0.f, 0.f);
        for (int jb = 0; jb < len; jb += 32) {
            int nb = 0;
            if (jb + lane < len) nb = g_adj[clampi(start + jb + lane, 0, NADJ - 1)];
            int m = min(32, len - jb);
            for (int k = 0; k < m; k++) {
                int id = __shfl_sync(0xffffffffu, nb, k);
                float2 v = *(const float2*)(src + (size_t)id * DQ + 2 * lane);
                acc.x += v.x; acc.y += v.y;
            }
        }
        float inv = 1.0f / (float)max(len, 1);
        float* d = dst + (size_t)node * DQ + 2 * lane;
        d[0] = acc.x * inv;
        d[1] = acc.y * inv;
    }
}

// ---------------- node transform: x = relu?( agg@Wl + b + x@Wr ) -------------
// Warp per row; lane owns output cols {lane, lane+32}. Both products fold into
// one accumulator pair per column (same output element). Weights k-pair
// interleaved in shared so the packed f32x2 operand comes from float4 loads.
template <bool RELU, bool USER>
__global__ void __launch_bounds__(256) k_transform(const float* __restrict__ Wl,
                                                   const float* __restrict__ bias,
                                                   const float* __restrict__ Wr) {
    __shared__ __align__(16) float wls[32 * 128];
    __shared__ __align__(16) float wrs[32 * 128];
    const float* agg = USER ? g_agg_u : g_agg_i;
    float*       x   = USER ? g_xu : g_xi;
    const int    n   = USER ? NUQ : NIQ;

    int tid = threadIdx.x, lane = tid & 31, warp = tid >> 5;
    for (int idx = tid; idx < 32 * 64; idx += 256) {
        int p = idx >> 6, d = idx & 63;
        *(float2*)&wls[p * 128 + 2 * d] = make_float2(Wl[2 * p * 64 + d], Wl[(2 * p + 1) * 64 + d]);
        *(float2*)&wrs[p * 128 + 2 * d] = make_float2(Wr[2 * p * 64 + d], Wr[(2 * p + 1) * 64 + d]);
    }
    float b0 = bias[lane], b1 = bias[lane + 32];
    __syncthreads();

    for (int row = blockIdx.x * 8 + warp; row < n; row += gridDim.x * 8) {
        const float4* arow = (const float4*)(agg + (size_t)row * DQ);
        const float4* xrow = (const float4*)(x + (size_t)row * DQ);
        u64 acc0 = 0, acc1 = 0;
#pragma unroll
        for (int q = 0; q < 16; q++) {
            float4 av = arow[q];
            float4 xv = xrow[q];
            int p = 2 * q;
            u64 a01 = pack2(av.x, av.y), a23 = pack2(av.z, av.w);
            u64 x01 = pack2(xv.x, xv.y), x23 = pack2(xv.z, xv.w);
            fma2(acc0, a01, *(const u64*)&wls[p * 128 + 2 * lane]);
            fma2(acc1, a01, *(const u64*)&wls[p * 128 + 2 * lane + 64]);
            fma2(acc0, x01, *(const u64*)&wrs[p * 128 + 2 * lane]);
            fma2(acc1, x01, *(const u64*)&wrs[p * 128 + 2 * lane + 64]);
            fma2(acc0, a23, *(const u64*)&wls[(p + 1) * 128 + 2 * lane]);
            fma2(acc1, a23, *(const u64*)&wls[(p + 1) * 128 + 2 * lane + 64]);
            fma2(acc0, x23, *(const u64*)&wrs[(p + 1) * 128 + 2 * lane]);
            fma2(acc1, x23, *(const u64*)&wrs[(p + 1) * 128 + 2 * lane + 64]);
        }
        float2 A0 = unpack2(acc0), A1 = unpack2(acc1);
        float o0 = b0 + A0.x + A0.y;
        float o1 = b1 + A1.x + A1.y;
        if (RELU) { o0 = fmaxf(o0, 0.f); o1 = fmaxf(o1, 0.f); }
        x[(size_t)row * DQ + lane]      = o0;
        x[(size_t)row * DQ + lane + 32] = o1;
    }
}

// ---------------- predictor: out[e] = dot(hu[lsrc[e]], hi[ldst[e]]) ----------
__global__ void k_dot(const int* __restrict__ lsrc, const int* __restrict__ ldst,
                      float* __restrict__ out) {
    int t = blockIdx.x * blockDim.x + threadIdx.x;
    int e = t >> 3;   // 8 lanes per edge; grid sized exactly
    int c = t & 7;
    int su = clampi(__ldg(&lsrc[e]), 0, NUQ - 1);
    int si = clampi(__ldg(&ldst[e]), 0, NIQ - 1);
    const float4* a = (const float4*)(g_xu + (size_t)su * DQ);
    const float4* b = (const float4*)(g_xi + (size_t)si * DQ);
    float4 a0 = a[2 * c], a1 = a[2 * c + 1];
    float4 b0 = b[2 * c], b1 = b[2 * c + 1];
    float s = a0.x * b0.x;
    s = fmaf(a0.y, b0.y, s); s = fmaf(a0.z, b0.z, s); s = fmaf(a0.w, b0.w, s);
    s = fmaf(a1.x, b1.x, s); s = fmaf(a1.y, b1.y, s);
    s = fmaf(a1.z, b1.z, s); s = fmaf(a1.w, b1.w, s);
    s += __shfl_down_sync(0xffffffffu, s, 4, 8);
    s += __shfl_down_sync(0xffffffffu, s, 2, 8);
    s += __shfl_down_sync(0xffffffffu, s, 1, 8);
    if (c == 0) out[e] = s;
}

// ---------------- launch ----------------
extern "C" void kernel_launch(void* const* d_in, const int* in_sizes, int n_in,
                              void* d_out, int out_size) {
    (void)in_sizes; (void)n_in; (void)out_size;
    const float* user_emb   = (const float*)d_in[0];
    const float* item_x     = (const float*)d_in[1];
    const float* item_lin_w = (const float*)d_in[2];
    const float* item_lin_b = (const float*)d_in[3];
    const float* Wl1_ui = (const float*)d_in[4];
    const float* Wr1_ui = (const float*)d_in[5];
    const float* b1_ui  = (const float*)d_in[6];
    const float* Wl1_iu = (const float*)d_in[7];
    const float* Wr1_iu = (const float*)d_in[8];
    const float* b1_iu  = (const float*)d_in[9];
    const float* Wl2_ui = (const float*)d_in[10];
    const float* Wr2_ui = (const float*)d_in[11];
    const float* b2_ui  = (const float*)d_in[12];
    const float* Wl2_iu = (const float*)d_in[13];
    const float* Wr2_iu = (const float*)d_in[14];
    const float* b2_iu  = (const float*)d_in[15];
    const int* uid  = (const int*)d_in[16];
    const int* esrc = (const int*)d_in[17];
    const int* edst = (const int*)d_in[18];
    const int* lsrc = (const int*)d_in[19];
    const int* ldst = (const int*)d_in[20];
    float* out = (float*)d_out;

    // ---- CSR build (graph identical for both layers -> built once) ----
    k_zero_cnt<<<1024, 256>>>();
    k_count<<<(NE + 255) / 256, 256>>>(esrc, edst);
    k_scan1<<<NBLK, 1024>>>();
    k_scan2<<<1, 512>>>();
    k_scan3<<<NBLK, 1024>>>();
    k_fill<<<(NE + 255) / 256, 256>>>(esrc, edst);

    // ---- input layers ----
    k_gather_user<<<(NUQ * 16) / 256, 256>>>((const float4*)user_emb, uid);
    k_itemlin<<<NIQ / 32, 256>>>(item_x, item_lin_w, item_lin_b);

    // ---- layer 1 (with ReLU) ----
    k_agg<true ><<<888, 256>>>();   // users <- mean of item rows
    k_agg<false><<<888, 256>>>();   // items <- mean of user rows
    k_transform<true,  true ><<<888, 256>>>(Wl1_iu, b1_iu, Wr1_iu);
    k_transform<true,  false><<<888, 256>>>(Wl1_ui, b1_ui, Wr1_ui);

    // ---- layer 2 (no ReLU) ----
    k_agg<true ><<<888, 256>>>();
    k_agg<false><<<888, 256>>>();
    k_transform<false, true ><<<888, 256>>>(Wl2_iu, b2_iu, Wr2_iu);
    k_transform<false, false><<<888, 256>>>(Wl2_ui, b2_ui, Wr2_ui);

    // ---- predictor ----
    k_dot<<<(NL * 8) / 256, 256>>>(lsrc, ldst, out);
}

// round 11
// speedup vs baseline: 1.4689x; 1.4689x over previous
#include <cuda_runtime.h>
#include <cstddef>

#define NUQ 500000
#define NIQ 100000
#define FDIM 300
#define DQ 64
#define NE 2000000
#define NL 1000000
#define NTOT (NUQ + NIQ)      // 600000
#define NADJ (2 * NE)         // 4000000
#define NBLK 293              // ceil(NTOT / 2048)

typedef unsigned long long u64;

// ---------------- device scratch (no runtime allocation allowed) ----------------
__device__ __align__(16) float g_xu[(size_t)NUQ * DQ];     // user features (in-place per layer)
__device__ __align__(16) float g_xi[(size_t)NIQ * DQ];     // item features (in-place per layer)
__device__ __align__(16) float g_agg_u[(size_t)NUQ * DQ];  // mean of item msgs at users
__device__ __align__(16) float g_agg_i[(size_t)NIQ * DQ];  // mean of user msgs at items
__device__ int g_cnt[NTOT];       // degrees: users [0,NU), items [NU,NU+NI)
__device__ int g_off[NTOT];       // exclusive scan of g_cnt
__device__ int g_cur[NTOT];       // fill cursors
__device__ int g_adj[NADJ];       // user buckets hold item ids; item buckets hold user ids
__device__ int g_bsum[NBLK];

// ---------------- helpers ----------------
__device__ __forceinline__ void fma2(u64& acc, u64 a, u64 b) {
    asm("fma.rn.f32x2 %0, %1, %2, %0;" : "+l"(acc) : "l"(a), "l"(b));
}
__device__ __forceinline__ u64 pack2(float x, float y) {
    u64 r; asm("mov.b64 %0, {%1, %2};" : "=l"(r) : "f"(x), "f"(y)); return r;
}
__device__ __forceinline__ float2 unpack2(u64 v) {
    float2 r; asm("mov.b64 {%0, %1}, %2;" : "=f"(r.x), "=f"(r.y) : "l"(v)); return r;
}
__device__ __forceinline__ int clampi(int v, int lo, int hi) {
    return min(max(v, lo), hi);
}
__device__ __forceinline__ int warp_incl_scan(int v) {
    int lane = threadIdx.x & 31;
#pragma unroll
    for (int d = 1; d < 32; d <<= 1) {
        int n = __shfl_up_sync(0xffffffffu, v, d);
        if (lane >= d) v += n;
    }
    return v;
}

// ---------------- CSR build ----------------
__global__ void k_zero_cnt() {
    for (int i = blockIdx.x * blockDim.x + threadIdx.x; i < NTOT;
         i += gridDim.x * blockDim.x) g_cnt[i] = 0;
}

__global__ void k_count(const int* __restrict__ esrc, const int* __restrict__ edst) {
    int e = blockIdx.x * blockDim.x + threadIdx.x;
    if (e >= NE) return;
    int u  = clampi(esrc[e], 0, NUQ - 1);
    int it = clampi(edst[e], 0, NIQ - 1);
    atomicAdd(&g_cnt[u], 1);
    atomicAdd(&g_cnt[NUQ + it], 1);
}

// 3-phase exclusive scan of g_cnt -> g_off (chunk = 2048 per block)
__global__ void __launch_bounds__(1024) k_scan1() {
    __shared__ int wsum[32];
    int t = threadIdx.x, lane = t & 31, w = t >> 5;
    int i0 = blockIdx.x * 2048 + 2 * t;
    int a = (i0 < NTOT)     ? g_cnt[i0]     : 0;
    int b = (i0 + 1 < NTOT) ? g_cnt[i0 + 1] : 0;
    int s = a + b;
    int incl = warp_incl_scan(s);
    if (lane == 31) wsum[w] = incl;
    __syncthreads();
    if (w == 0) {
        int ws = wsum[lane];
        int wincl = warp_incl_scan(ws);
        wsum[lane] = wincl - ws;                       // exclusive warp offset
        if (lane == 31) g_bsum[blockIdx.x] = wincl;    // block total
    }
    __syncthreads();
    int excl = incl - s + wsum[w];
    if (i0 < NTOT)     g_off[i0]     = excl;
    if (i0 + 1 < NTOT) g_off[i0 + 1] = excl + a;
}

__global__ void __launch_bounds__(512) k_scan2() {   // scans NBLK(<=512) block sums
    __shared__ int wsum[16];
    int t = threadIdx.x, lane = t & 31, w = t >> 5;
    int v0 = (t < NBLK) ? g_bsum[t] : 0;
    int incl = warp_incl_scan(v0);
    if (lane == 31) wsum[w] = incl;
    __syncthreads();
    if (w == 0 && lane < 16) {
        int ws = wsum[lane];
        int wincl = ws;
#pragma unroll
        for (int d = 1; d < 16; d <<= 1) {
            int n = __shfl_up_sync(0x0000ffffu, wincl, d, 16);
            if (lane >= d) wincl += n;
        }
        wsum[lane] = wincl - ws;
    }
    __syncthreads();
    if (t < NBLK) g_bsum[t] = incl - v0 + wsum[w];
}

__global__ void __launch_bounds__(1024) k_scan3() {
    int add = g_bsum[blockIdx.x];
    int i = blockIdx.x * 2048 + threadIdx.x;
#pragma unroll
    for (int r = 0; r < 2; r++, i += 1024) {
        if (i < NTOT) { int o = g_off[i] + add; g_off[i] = o; g_cur[i] = o; }
    }
}

__global__ void k_fill(const int* __restrict__ esrc, const int* __restrict__ edst) {
    int e = blockIdx.x * blockDim.x + threadIdx.x;
    if (e >= NE) return;
    int u  = clampi(esrc[e], 0, NUQ - 1);
    int it = clampi(edst[e], 0, NIQ - 1);
    int p1 = clampi(atomicAdd(&g_cur[u], 1),        0, NADJ - 1);
    int p2 = clampi(atomicAdd(&g_cur[NUQ + it], 1), 0, NADJ - 1);
    g_adj[p1] = it;   // user bucket: neighbor item ids
    g_adj[p2] = u;    // item bucket: neighbor user ids
}

// ---------------- input layers ----------------
// x_user = user_emb_w[user_node_id]  (faithful gather; one float4 per thread)
__global__ void k_gather_user(const float4* __restrict__ emb, const int* __restrict__ uid) {
    size_t i = blockIdx.x * (size_t)blockDim.x + threadIdx.x;  // over NUQ*16 float4s
    int row = (int)(i >> 4);
    int c = (int)(i & 15);
    int id = clampi(uid[row], 0, NUQ - 1);
    ((float4*)g_xu)[i] = emb[(size_t)id * 16 + c];
}

// g_xi = item_x @ W + b. Warp computes 4 rows; W staged in shared in
// k-pair-interleaved layout so each fma.rn.f32x2 consumes a packed x pair.
__global__ void __launch_bounds__(256) k_itemlin(const float* __restrict__ x,
                                                 const float* __restrict__ W,
                                                 const float* __restrict__ b) {
    __shared__ __align__(16) float ws[75 * 128];  // 150 k's per chunk: 75 pairs x 64 d x 2
    int tid = threadIdx.x, lane = tid & 31, warp = tid >> 5;
    int row0 = (blockIdx.x * 8 + warp) * 4;

    u64 acc[4][2];
#pragma unroll
    for (int r = 0; r < 4; r++) { acc[r][0] = 0ull; acc[r][1] = 0ull; }

    for (int chunk = 0; chunk < 2; chunk++) {
        if (chunk) __syncthreads();
        for (int idx = tid; idx < 75 * 64; idx += 256) {
            int p = idx >> 6, d = idx & 63;
            int k = chunk * 150 + 2 * p;
            *(float2*)&ws[p * 128 + 2 * d] = make_float2(W[k * 64 + d], W[(k + 1) * 64 + d]);
        }
        __syncthreads();
        const float* xb = x + (size_t)row0 * FDIM + chunk * 150;
        for (int p = 0; p < 75; p++) {
            u64 w0 = *(const u64*)&ws[p * 128 + 2 * lane];
            u64 w1 = *(const u64*)&ws[p * 128 + 2 * lane + 64];
#pragma unroll
            for (int r = 0; r < 4; r++) {
                float2 xf = *(const float2*)(xb + (size_t)r * FDIM + 2 * p);
                u64 xv = pack2(xf.x, xf.y);
                fma2(acc[r][0], xv, w0);
                fma2(acc[r][1], xv, w1);
            }
        }
    }
    float b0 = b[lane], b1 = b[lane + 32];
#pragma unroll
    for (int r = 0; r < 4; r++) {
        float2 a0 = unpack2(acc[r][0]), a1 = unpack2(acc[r][1]);
        g_xi[(size_t)(row0 + r) * DQ + lane]      = b0 + a0.x + a0.y;
        g_xi[(size_t)(row0 + r) * DQ + lane + 32] = b1 + a1.x + a1.y;
    }
}

// ---------------- aggregation (gather over CSR): agg = mean of neighbor rows --
// Unrolled-by-4 neighbor loop with 4 independent accumulator pairs -> MLP=4
// per warp instead of a serial shfl->LDG->FADD chain per neighbor.
template <bool USER>
__global__ void __launch_bounds__(256) k_agg() {
    int gw = (blockIdx.x * blockDim.x + threadIdx.x) >> 5;
    int lane = threadIdx.x & 31;
    int nwarp = (gridDim.x * blockDim.x) >> 5;
    const int n = USER ? NUQ : NIQ;
    const float* __restrict__ src = USER ? g_xi : g_xu;
    float* __restrict__ dst       = USER ? g_agg_u : g_agg_i;

    for (int node = gw; node < n; node += nwarp) {
        int key = USER ? node : NUQ + node;
        int start = g_off[key];
        int len = g_cnt[key];
        float2 a0 = make_float2(0.f, 0.f), a1 = a0, a2 = a0, a3 = a0;
        for (int jb = 0; jb < len; jb += 32) {
            int nb = 0;
            if (jb + lane < len) nb = g_adj[start + jb + lane];
            int m = min(32, len - jb);
            int k = 0;
            for (; k + 4 <= m; k += 4) {
                int i0 = __shfl_sync(0xffffffffu, nb, k);
                int i1 = __shfl_sync(0xffffffffu, nb, k + 1);
                int i2 = __shfl_sync(0xffffffffu, nb, k + 2);
                int i3 = __shfl_sync(0xffffffffu, nb, k + 3);
                float2 v0 = *(const float2*)(src + (size_t)i0 * DQ + 2 * lane);
                float2 v1 = *(const float2*)(src + (size_t)i1 * DQ + 2 * lane);
                float2 v2 = *(const float2*)(src + (size_t)i2 * DQ + 2 * lane);
                float2 v3 = *(const float2*)(src + (size_t)i3 * DQ + 2 * lane);
                a0.x += v0.x; a0.y += v0.y;
                a1.x += v1.x; a1.y += v1.y;
                a2.x += v2.x; a2.y += v2.y;
                a3.x += v3.x; a3.y += v3.y;
            }
            for (; k < m; k++) {
                int id = __shfl_sync(0xffffffffu, nb, k);
                float2 v = *(const float2*)(src + (size_t)id * DQ + 2 * lane);
                a0.x += v.x; a0.y += v.y;
            }
        }
        float inv = 1.0f / (float)max(len, 1);
        float sx = (a0.x + a1.x) + (a2.x + a3.x);
        float sy = (a0.y + a1.y) + (a2.y + a3.y);
        float* d = dst + (size_t)node * DQ + 2 * lane;
        d[0] = sx * inv;
        d[1] = sy * inv;
    }
}

// ---------------- node transform: x = relu?( agg@Wl + b + x@Wr ) -------------
// Warp per 4-row group; lane owns output cols {lane, lane+32}. 4-row blocking
// reuses every weight LDS.64 across 4 rows, dropping the smem-port cost from
// 4x the fma-issue floor to parity with it. Weights k-pair interleaved in
// shared so the packed f32x2 operand comes straight from float4 loads.
template <bool RELU, bool USER>
__global__ void __launch_bounds__(256) k_transform(const float* __restrict__ Wl,
                                                   const float* __restrict__ bias,
                                                   const float* __restrict__ Wr) {
    __shared__ __align__(16) float wls[32 * 128];
    __shared__ __align__(16) float wrs[32 * 128];
    const float* agg = USER ? g_agg_u : g_agg_i;
    float*       x   = USER ? g_xu : g_xi;
    const int    ngrp = (USER ? NUQ : NIQ) / 4;   // both divisible by 4

    int tid = threadIdx.x, lane = tid & 31, warp = tid >> 5;
    for (int idx = tid; idx < 32 * 64; idx += 256) {
        int p = idx >> 6, d = idx & 63;
        *(float2*)&wls[p * 128 + 2 * d] = make_float2(Wl[2 * p * 64 + d], Wl[(2 * p + 1) * 64 + d]);
        *(float2*)&wrs[p * 128 + 2 * d] = make_float2(Wr[2 * p * 64 + d], Wr[(2 * p + 1) * 64 + d]);
    }
    float b0 = bias[lane], b1 = bias[lane + 32];
    __syncthreads();

    for (int g = blockIdx.x * 8 + warp; g < ngrp; g += gridDim.x * 8) {
        int row0 = g * 4;
        const float4* arow = (const float4*)(agg + (size_t)row0 * DQ);
        const float4* xrow = (const float4*)(x + (size_t)row0 * DQ);
        u64 acc[4][2];
#pragma unroll
        for (int r = 0; r < 4; r++) { acc[r][0] = 0ull; acc[r][1] = 0ull; }

#pragma unroll
        for (int q = 0; q < 16; q++) {
            int p = 2 * q;
            u64 wl0a = *(const u64*)&wls[p * 128 + 2 * lane];
            u64 wl1a = *(const u64*)&wls[p * 128 + 2 * lane + 64];
            u64 wr0a = *(const u64*)&wrs[p * 128 + 2 * lane];
            u64 wr1a = *(const u64*)&wrs[p * 128 + 2 * lane + 64];
            u64 wl0b = *(const u64*)&wls[(p + 1) * 128 + 2 * lane];
            u64 wl1b = *(const u64*)&wls[(p + 1) * 128 + 2 * lane + 64];
            u64 wr0b = *(const u64*)&wrs[(p + 1) * 128 + 2 * lane];
            u64 wr1b = *(const u64*)&wrs[(p + 1) * 128 + 2 * lane + 64];
#pragma unroll
            for (int r = 0; r < 4; r++) {
                float4 av = arow[r * 16 + q];
                float4 xv = xrow[r * 16 + q];
                u64 av01 = pack2(av.x, av.y), av23 = pack2(av.z, av.w);
                u64 xv01 = pack2(xv.x, xv.y), xv23 = pack2(xv.z, xv.w);
                fma2(acc[r][0], av01, wl0a);
                fma2(acc[r][1], av01, wl1a);
                fma2(acc[r][0], xv01, wr0a);
                fma2(acc[r][1], xv01, wr1a);
                fma2(acc[r][0], av23, wl0b);
                fma2(acc[r][1], av23, wl1b);
                fma2(acc[r][0], xv23, wr0b);
                fma2(acc[r][1], xv23, wr1b);
            }
        }
#pragma unroll
        for (int r = 0; r < 4; r++) {
            float2 A0 = unpack2(acc[r][0]), A1 = unpack2(acc[r][1]);
            float o0 = b0 + A0.x + A0.y;
            float o1 = b1 + A1.x + A1.y;
            if (RELU) { o0 = fmaxf(o0, 0.f); o1 = fmaxf(o1, 0.f); }
            x[(size_t)(row0 + r) * DQ + lane]      = o0;
            x[(size_t)(row0 + r) * DQ + lane + 32] = o1;
        }
    }
}

// ---------------- predictor: out[e] = dot(hu[lsrc[e]], hi[ldst[e]]) ----------
__global__ void k_dot(const int* __restrict__ lsrc, const int* __restrict__ ldst,
                      float* __restrict__ out) {
    int t = blockIdx.x * blockDim.x + threadIdx.x;
    int e = t >> 3;   // 8 lanes per edge; grid sized exactly
    int c = t & 7;
    int su = clampi(__ldg(&lsrc[e]), 0, NUQ - 1);
    int si = clampi(__ldg(&ldst[e]), 0, NIQ - 1);
    const float4* a = (const float4*)(g_xu + (size_t)su * DQ);
    const float4* b = (const float4*)(g_xi + (size_t)si * DQ);
    float4 a0 = a[2 * c], a1 = a[2 * c + 1];
    float4 b0 = b[2 * c], b1 = b[2 * c + 1];
    float s = a0.x * b0.x;
    s = fmaf(a0.y, b0.y, s); s = fmaf(a0.z, b0.z, s); s = fmaf(a0.w, b0.w, s);
    s = fmaf(a1.x, b1.x, s); s = fmaf(a1.y, b1.y, s);
    s = fmaf(a1.z, b1.z, s); s = fmaf(a1.w, b1.w, s);
    s += __shfl_down_sync(0xffffffffu, s, 4, 8);
    s += __shfl_down_sync(0xffffffffu, s, 2, 8);
    s += __shfl_down_sync(0xffffffffu, s, 1, 8);
    if (c == 0) out[e] = s;
}

// ---------------- launch ----------------
extern "C" void kernel_launch(void* const* d_in, const int* in_sizes, int n_in,
                              void* d_out, int out_size) {
    (void)in_sizes; (void)n_in; (void)out_size;
    const float* user_emb   = (const float*)d_in[0];
    const float* item_x     = (const float*)d_in[1];
    const float* item_lin_w = (const float*)d_in[2];
    const float* item_lin_b = (const float*)d_in[3];
    const float* Wl1_ui = (const float*)d_in[4];
    const float* Wr1_ui = (const float*)d_in[5];
    const float* b1_ui  = (const float*)d_in[6];
    const float* Wl1_iu = (const float*)d_in[7];
    const float* Wr1_iu = (const float*)d_in[8];
    const float* b1_iu  = (const float*)d_in[9];
    const float* Wl2_ui = (const float*)d_in[10];
    const float* Wr2_ui = (const float*)d_in[11];
    const float* b2_ui  = (const float*)d_in[12];
    const float* Wl2_iu = (const float*)d_in[13];
    const float* Wr2_iu = (const float*)d_in[14];
    const float* b2_iu  = (const float*)d_in[15];
    const int* uid  = (const int*)d_in[16];
    const int* esrc = (const int*)d_in[17];
    const int* edst = (const int*)d_in[18];
    const int* lsrc = (const int*)d_in[19];
    const int* ldst = (const int*)d_in[20];
    float* out = (float*)d_out;

    // ---- CSR build (graph identical for both layers -> built once) ----
    k_zero_cnt<<<1024, 256>>>();
    k_count<<<(NE + 255) / 256, 256>>>(esrc, edst);
    k_scan1<<<NBLK, 1024>>>();
    k_scan2<<<1, 512>>>();
    k_scan3<<<NBLK, 1024>>>();
    k_fill<<<(NE + 255) / 256, 256>>>(esrc, edst);

    // ---- input layers ----
    k_gather_user<<<(NUQ * 16) / 256, 256>>>((const float4*)user_emb, uid);
    k_itemlin<<<NIQ / 32, 256>>>(item_x, item_lin_w, item_lin_b);

    // ---- layer 1 (with ReLU) ----
    k_agg<true ><<<888, 256>>>();   // users <- mean of item rows
    k_agg<false><<<888, 256>>>();   // items <- mean of user rows
    k_transform<true,  true ><<<888, 256>>>(Wl1_iu, b1_iu, Wr1_iu);
    k_transform<true,  false><<<888, 256>>>(Wl1_ui, b1_ui, Wr1_ui);

    // ---- layer 2 (no ReLU) ----
    k_agg<true ><<<888, 256>>>();
    k_agg<false><<<888, 256>>>();
    k_transform<false, true ><<<888, 256>>>(Wl2_iu, b2_iu, Wr2_iu);
    k_transform<false, false><<<888, 256>>>(Wl2_ui, b2_ui, Wr2_ui);

    // ---- predictor ----
    k_dot<<<(NL * 8) / 256, 256>>>(lsrc, ldst, out);
}

// round 12
// speedup vs baseline: 1.9912x; 1.3556x over previous
#include <cuda_runtime.h>
#include <cstddef>

#define NUQ 500000
#define NIQ 100000
#define FDIM 300
#define DQ 64
#define NE 2000000
#define NL 1000000
#define NTOT (NUQ + NIQ)      // 600000
#define NADJ (2 * NE)         // 4000000
#define NBLK 293              // ceil(NTOT / 2048)

typedef unsigned long long u64;

// ---------------- device scratch (no runtime allocation allowed) ----------------
__device__ __align__(16) float g_xu[(size_t)NUQ * DQ];     // user features (in-place per layer)
__device__ __align__(16) float g_xi[(size_t)NIQ * DQ];     // item features (in-place per layer)
__device__ __align__(16) float g_agg_u[(size_t)NUQ * DQ];  // mean of item msgs at users
__device__ __align__(16) float g_agg_i[(size_t)NIQ * DQ];  // mean of user msgs at items
__device__ int  g_cnt[NTOT];      // degrees: users [0,NU), items [NU,NU+NI)
__device__ int  g_off[NTOT];      // exclusive scan of g_cnt (scan scratch)
__device__ int  g_cur[NTOT];      // fill cursors
__device__ int2 g_meta[NTOT];     // {offset, count} fused for one-load access
__device__ int  g_adj[NADJ];      // user buckets hold item ids; item buckets hold user ids
__device__ int  g_bsum[NBLK];

// ---------------- helpers ----------------
__device__ __forceinline__ void fma2(u64& acc, u64 a, u64 b) {
    asm("fma.rn.f32x2 %0, %1, %2, %0;" : "+l"(acc) : "l"(a), "l"(b));
}
__device__ __forceinline__ u64 pack2(float x, float y) {
    u64 r; asm("mov.b64 %0, {%1, %2};" : "=l"(r) : "f"(x), "f"(y)); return r;
}
__device__ __forceinline__ float2 unpack2(u64 v) {
    float2 r; asm("mov.b64 {%0, %1}, %2;" : "=f"(r.x), "=f"(r.y) : "l"(v)); return r;
}
__device__ __forceinline__ int clampi(int v, int lo, int hi) {
    return min(max(v, lo), hi);
}
__device__ __forceinline__ int warp_incl_scan(int v) {
    int lane = threadIdx.x & 31;
#pragma unroll
    for (int d = 1; d < 32; d <<= 1) {
        int n = __shfl_up_sync(0xffffffffu, v, d);
        if (lane >= d) v += n;
    }
    return v;
}

// ---------------- CSR build ----------------
__global__ void k_zero_cnt() {
    for (int i = blockIdx.x * blockDim.x + threadIdx.x; i < NTOT;
         i += gridDim.x * blockDim.x) g_cnt[i] = 0;
}

__global__ void k_count(const int* __restrict__ esrc, const int* __restrict__ edst) {
    int e = blockIdx.x * blockDim.x + threadIdx.x;
    if (e >= NE) return;
    int u  = clampi(esrc[e], 0, NUQ - 1);
    int it = clampi(edst[e], 0, NIQ - 1);
    atomicAdd(&g_cnt[u], 1);
    atomicAdd(&g_cnt[NUQ + it], 1);
}

// 3-phase exclusive scan of g_cnt -> g_off (chunk = 2048 per block)
__global__ void __launch_bounds__(1024) k_scan1() {
    __shared__ int wsum[32];
    int t = threadIdx.x, lane = t & 31, w = t >> 5;
    int i0 = blockIdx.x * 2048 + 2 * t;
    int a = (i0 < NTOT)     ? g_cnt[i0]     : 0;
    int b = (i0 + 1 < NTOT) ? g_cnt[i0 + 1] : 0;
    int s = a + b;
    int incl = warp_incl_scan(s);
    if (lane == 31) wsum[w] = incl;
    __syncthreads();
    if (w == 0) {
        int ws = wsum[lane];
        int wincl = warp_incl_scan(ws);
        wsum[lane] = wincl - ws;                       // exclusive warp offset
        if (lane == 31) g_bsum[blockIdx.x] = wincl;    // block total
    }
    __syncthreads();
    int excl = incl - s + wsum[w];
    if (i0 < NTOT)     g_off[i0]     = excl;
    if (i0 + 1 < NTOT) g_off[i0 + 1] = excl + a;
}

__global__ void __launch_bounds__(512) k_scan2() {   // scans NBLK(<=512) block sums
    __shared__ int wsum[16];
    int t = threadIdx.x, lane = t & 31, w = t >> 5;
    int v0 = (t < NBLK) ? g_bsum[t] : 0;
    int incl = warp_incl_scan(v0);
    if (lane == 31) wsum[w] = incl;
    __syncthreads();
    if (w == 0 && lane < 16) {
        int ws = wsum[lane];
        int wincl = ws;
#pragma unroll
        for (int d = 1; d < 16; d <<= 1) {
            int n = __shfl_up_sync(0x0000ffffu, wincl, d, 16);
            if (lane >= d) wincl += n;
        }
        wsum[lane] = wincl - ws;
    }
    __syncthreads();
    if (t < NBLK) g_bsum[t] = incl - v0 + wsum[w];
}

__global__ void __launch_bounds__(1024) k_scan3() {
    int add = g_bsum[blockIdx.x];
    int i = blockIdx.x * 2048 + threadIdx.x;
#pragma unroll
    for (int r = 0; r < 2; r++, i += 1024) {
        if (i < NTOT) {
            int o = g_off[i] + add;
            g_cur[i]  = o;
            g_meta[i] = make_int2(o, g_cnt[i]);
        }
    }
}

__global__ void k_fill(const int* __restrict__ esrc, const int* __restrict__ edst) {
    int e = blockIdx.x * blockDim.x + threadIdx.x;
    if (e >= NE) return;
    int u  = clampi(esrc[e], 0, NUQ - 1);
    int it = clampi(edst[e], 0, NIQ - 1);
    int p1 = clampi(atomicAdd(&g_cur[u], 1),        0, NADJ - 1);
    int p2 = clampi(atomicAdd(&g_cur[NUQ + it], 1), 0, NADJ - 1);
    g_adj[p1] = it;   // user bucket: neighbor item ids
    g_adj[p2] = u;    // item bucket: neighbor user ids
}

// ---------------- input layers ----------------
// x_user = user_emb_w[user_node_id]  (faithful gather; one float4 per thread)
__global__ void k_gather_user(const float4* __restrict__ emb, const int* __restrict__ uid) {
    size_t i = blockIdx.x * (size_t)blockDim.x + threadIdx.x;  // over NUQ*16 float4s
    int row = (int)(i >> 4);
    int c = (int)(i & 15);
    int id = clampi(uid[row], 0, NUQ - 1);
    ((float4*)g_xu)[i] = emb[(size_t)id * 16 + c];
}

// g_xi = item_x @ W + b. Warp computes 4 rows; W staged in shared in
// k-pair-interleaved layout so each fma.rn.f32x2 consumes a packed x pair.
__global__ void __launch_bounds__(256) k_itemlin(const float* __restrict__ x,
                                                 const float* __restrict__ W,
                                                 const float* __restrict__ b) {
    __shared__ __align__(16) float ws[75 * 128];  // 150 k's per chunk: 75 pairs x 64 d x 2
    int tid = threadIdx.x, lane = tid & 31, warp = tid >> 5;
    int row0 = (blockIdx.x * 8 + warp) * 4;

    u64 acc[4][2];
#pragma unroll
    for (int r = 0; r < 4; r++) { acc[r][0] = 0ull; acc[r][1] = 0ull; }

    for (int chunk = 0; chunk < 2; chunk++) {
        if (chunk) __syncthreads();
        for (int idx = tid; idx < 75 * 64; idx += 256) {
            int p = idx >> 6, d = idx & 63;
            int k = chunk * 150 + 2 * p;
            *(float2*)&ws[p * 128 + 2 * d] = make_float2(W[k * 64 + d], W[(k + 1) * 64 + d]);
        }
        __syncthreads();
        const float* xb = x + (size_t)row0 * FDIM + chunk * 150;
#pragma unroll 5
        for (int p = 0; p < 75; p++) {
            u64 w0 = *(const u64*)&ws[p * 128 + 2 * lane];
            u64 w1 = *(const u64*)&ws[p * 128 + 2 * lane + 64];
#pragma unroll
            for (int r = 0; r < 4; r++) {
                float2 xf = *(const float2*)(xb + (size_t)r * FDIM + 2 * p);
                u64 xv = pack2(xf.x, xf.y);
                fma2(acc[r][0], xv, w0);
                fma2(acc[r][1], xv, w1);
            }
        }
    }
    float b0 = b[lane], b1 = b[lane + 32];
#pragma unroll
    for (int r = 0; r < 4; r++) {
        float2 a0 = unpack2(acc[r][0]), a1 = unpack2(acc[r][1]);
        g_xi[(size_t)(row0 + r) * DQ + lane]      = b0 + a0.x + a0.y;
        g_xi[(size_t)(row0 + r) * DQ + lane + 32] = b1 + a1.x + a1.y;
    }
}

// ---------------- aggregation (gather over CSR): agg = mean of neighbor rows --
// float4 lanes, 2 neighbors per warp-step (halves LDG instr count), fused
// {off,cnt} metadata load, 4 neighbors in flight in the unrolled path.
template <bool USER>
__global__ void __launch_bounds__(256) k_agg() {
    int gw = (blockIdx.x * blockDim.x + threadIdx.x) >> 5;
    int lane = threadIdx.x & 31;
    int nwarp = (gridDim.x * blockDim.x) >> 5;
    const int n = USER ? NUQ : NIQ;
    const float* __restrict__ src = USER ? g_xi : g_xu;
    float* __restrict__ dst       = USER ? g_agg_u : g_agg_i;
    const int base = USER ? 0 : NUQ;
    int half = lane >> 4;       // 0: even neighbor, 1: odd neighbor
    int c4 = lane & 15;         // float4 index within the 64-float row

    for (int node = gw; node < n; node += nwarp) {
        int2 oc = g_meta[base + node];
        int start = oc.x, len = oc.y;
        float4 accA = make_float4(0.f, 0.f, 0.f, 0.f);
        float4 accB = make_float4(0.f, 0.f, 0.f, 0.f);
        for (int jb = 0; jb < len; jb += 32) {
            int nb = 0;
            if (jb + lane < len) nb = g_adj[start + jb + lane];
            int m = min(32, len - jb);
            int k = 0;
            for (; k + 4 <= m; k += 4) {
                int i0 = __shfl_sync(0xffffffffu, nb, k);
                int i1 = __shfl_sync(0xffffffffu, nb, k + 1);
                int i2 = __shfl_sync(0xffffffffu, nb, k + 2);
                int i3 = __shfl_sync(0xffffffffu, nb, k + 3);
                int idA = half ? i1 : i0;
                int idB = half ? i3 : i2;
                float4 vA = *(const float4*)(src + (size_t)idA * DQ + c4 * 4);
                float4 vB = *(const float4*)(src + (size_t)idB * DQ + c4 * 4);
                accA.x += vA.x; accA.y += vA.y; accA.z += vA.z; accA.w += vA.w;
                accB.x += vB.x; accB.y += vB.y; accB.z += vB.z; accB.w += vB.w;
            }
            for (; k + 2 <= m; k += 2) {
                int i0 = __shfl_sync(0xffffffffu, nb, k);
                int i1 = __shfl_sync(0xffffffffu, nb, k + 1);
                int id = half ? i1 : i0;
                float4 v = *(const float4*)(src + (size_t)id * DQ + c4 * 4);
                accA.x += v.x; accA.y += v.y; accA.z += v.z; accA.w += v.w;
            }
            if (k < m) {   // single leftover: only half 0 contributes
                int i0 = __shfl_sync(0xffffffffu, nb, k);
                float4 v = *(const float4*)(src + (size_t)i0 * DQ + c4 * 4);
                if (!half) {
                    accA.x += v.x; accA.y += v.y; accA.z += v.z; accA.w += v.w;
                }
            }
        }
        float4 a = make_float4(accA.x + accB.x, accA.y + accB.y,
                               accA.z + accB.z, accA.w + accB.w);
        a.x += __shfl_down_sync(0xffffffffu, a.x, 16);
        a.y += __shfl_down_sync(0xffffffffu, a.y, 16);
        a.z += __shfl_down_sync(0xffffffffu, a.z, 16);
        a.w += __shfl_down_sync(0xffffffffu, a.w, 16);
        if (half == 0) {
            float inv = 1.0f / (float)max(len, 1);
            a.x *= inv; a.y *= inv; a.z *= inv; a.w *= inv;
            *(float4*)(dst + (size_t)node * DQ + c4 * 4) = a;
        }
    }
}

// ---------------- node transform: x = relu?( agg@Wl + b + x@Wr ) -------------
// Warp per 4-row group; lane owns output cols {lane, lane+32}. 4-row blocking
// reuses every weight LDS.64 across 4 rows. q-loop unroll capped at 4 so ptxas
// keeps ~16 outstanding LDGs (enough MLP) instead of front-batching 128 and
// spilling / saturating the L1tex wavefront queue.
template <bool RELU, bool USER>
__global__ void __launch_bounds__(256) k_transform(const float* __restrict__ Wl,
                                                   const float* __restrict__ bias,
                                                   const float* __restrict__ Wr) {
    __shared__ __align__(16) float wls[32 * 128];
    __shared__ __align__(16) float wrs[32 * 128];
    const float* agg = USER ? g_agg_u : g_agg_i;
    float*       x   = USER ? g_xu : g_xi;
    const int    ngrp = (USER ? NUQ : NIQ) / 4;   // both divisible by 4

    int tid = threadIdx.x, lane = tid & 31, warp = tid >> 5;
    for (int idx = tid; idx < 32 * 64; idx += 256) {
        int p = idx >> 6, d = idx & 63;
        *(float2*)&wls[p * 128 + 2 * d] = make_float2(Wl[2 * p * 64 + d], Wl[(2 * p + 1) * 64 + d]);
        *(float2*)&wrs[p * 128 + 2 * d] = make_float2(Wr[2 * p * 64 + d], Wr[(2 * p + 1) * 64 + d]);
    }
    float b0 = bias[lane], b1 = bias[lane + 32];
    __syncthreads();

    for (int g = blockIdx.x * 8 + warp; g < ngrp; g += gridDim.x * 8) {
        int row0 = g * 4;
        const float4* arow = (const float4*)(agg + (size_t)row0 * DQ);
        const float4* xrow = (const float4*)(x + (size_t)row0 * DQ);
        u64 acc[4][2];
#pragma unroll
        for (int r = 0; r < 4; r++) { acc[r][0] = 0ull; acc[r][1] = 0ull; }

#pragma unroll 4
        for (int q = 0; q < 16; q++) {
            int p = 2 * q;
            u64 wl0a = *(const u64*)&wls[p * 128 + 2 * lane];
            u64 wl1a = *(const u64*)&wls[p * 128 + 2 * lane + 64];
            u64 wr0a = *(const u64*)&wrs[p * 128 + 2 * lane];
            u64 wr1a = *(const u64*)&wrs[p * 128 + 2 * lane + 64];
            u64 wl0b = *(const u64*)&wls[(p + 1) * 128 + 2 * lane];
            u64 wl1b = *(const u64*)&wls[(p + 1) * 128 + 2 * lane + 64];
            u64 wr0b = *(const u64*)&wrs[(p + 1) * 128 + 2 * lane];
            u64 wr1b = *(const u64*)&wrs[(p + 1) * 128 + 2 * lane + 64];
#pragma unroll
            for (int r = 0; r < 4; r++) {
                float4 av = arow[r * 16 + q];
                float4 xv = xrow[r * 16 + q];
                u64 av01 = pack2(av.x, av.y), av23 = pack2(av.z, av.w);
                u64 xv01 = pack2(xv.x, xv.y), xv23 = pack2(xv.z, xv.w);
                fma2(acc[r][0], av01, wl0a);
                fma2(acc[r][1], av01, wl1a);
                fma2(acc[r][0], xv01, wr0a);
                fma2(acc[r][1], xv01, wr1a);
                fma2(acc[r][0], av23, wl0b);
                fma2(acc[r][1], av23, wl1b);
                fma2(acc[r][0], xv23, wr0b);
                fma2(acc[r][1], xv23, wr1b);
            }
        }
#pragma unroll
        for (int r = 0; r < 4; r++) {
            float2 A0 = unpack2(acc[r][0]), A1 = unpack2(acc[r][1]);
            float o0 = b0 + A0.x + A0.y;
            float o1 = b1 + A1.x + A1.y;
            if (RELU) { o0 = fmaxf(o0, 0.f); o1 = fmaxf(o1, 0.f); }
            x[(size_t)(row0 + r) * DQ + lane]      = o0;
            x[(size_t)(row0 + r) * DQ + lane + 32] = o1;
        }
    }
}

// ---------------- predictor: out[e] = dot(hu[lsrc[e]], hi[ldst[e]]) ----------
__global__ void k_dot(const int* __restrict__ lsrc, const int* __restrict__ ldst,
                      float* __restrict__ out) {
    int t = blockIdx.x * blockDim.x + threadIdx.x;
    int e = t >> 3;   // 8 lanes per edge; grid sized exactly
    int c = t & 7;
    int su = clampi(__ldg(&lsrc[e]), 0, NUQ - 1);
    int si = clampi(__ldg(&ldst[e]), 0, NIQ - 1);
    const float4* a = (const float4*)(g_xu + (size_t)su * DQ);
    const float4* b = (const float4*)(g_xi + (size_t)si * DQ);
    float4 a0 = a[2 * c], a1 = a[2 * c + 1];
    float4 b0 = b[2 * c], b1 = b[2 * c + 1];
    float s = a0.x * b0.x;
    s = fmaf(a0.y, b0.y, s); s = fmaf(a0.z, b0.z, s); s = fmaf(a0.w, b0.w, s);
    s = fmaf(a1.x, b1.x, s); s = fmaf(a1.y, b1.y, s);
    s = fmaf(a1.z, b1.z, s); s = fmaf(a1.w, b1.w, s);
    s += __shfl_down_sync(0xffffffffu, s, 4, 8);
    s += __shfl_down_sync(0xffffffffu, s, 2, 8);
    s += __shfl_down_sync(0xffffffffu, s, 1, 8);
    if (c == 0) out[e] = s;
}

// ---------------- launch ----------------
extern "C" void kernel_launch(void* const* d_in, const int* in_sizes, int n_in,
                              void* d_out, int out_size) {
    (void)in_sizes; (void)n_in; (void)out_size;
    const float* user_emb   = (const float*)d_in[0];
    const float* item_x     = (const float*)d_in[1];
    const float* item_lin_w = (const float*)d_in[2];
    const float* item_lin_b = (const float*)d_in[3];
    const float* Wl1_ui = (const float*)d_in[4];
    const float* Wr1_ui = (const float*)d_in[5];
    const float* b1_ui  = (const float*)d_in[6];
    const float* Wl1_iu = (const float*)d_in[7];
    const float* Wr1_iu = (const float*)d_in[8];
    const float* b1_iu  = (const float*)d_in[9];
    const float* Wl2_ui = (const float*)d_in[10];
    const float* Wr2_ui = (const float*)d_in[11];
    const float* b2_ui  = (const float*)d_in[12];
    const float* Wl2_iu = (const float*)d_in[13];
    const float* Wr2_iu = (const float*)d_in[14];
    const float* b2_iu  = (const float*)d_in[15];
    const int* uid  = (const int*)d_in[16];
    const int* esrc = (const int*)d_in[17];
    const int* edst = (const int*)d_in[18];
    const int* lsrc = (const int*)d_in[19];
    const int* ldst = (const int*)d_in[20];
    float* out = (float*)d_out;

    // Launch order note: ncu capture (-s 5 -c 1, after 2 harness launches)
    // profiles MY 4th launch -> put k_itemlin there for a useful profile.
    k_zero_cnt<<<1024, 256>>>();                                       // 0
    k_count<<<(NE + 255) / 256, 256>>>(esrc, edst);                    // 1
    k_gather_user<<<(NUQ * 16) / 256, 256>>>((const float4*)user_emb, uid);  // 2
    k_itemlin<<<NIQ / 32, 256>>>(item_x, item_lin_w, item_lin_b);      // 3 <- profiled
    k_scan1<<<NBLK, 1024>>>();
    k_scan2<<<1, 512>>>();
    k_scan3<<<NBLK, 1024>>>();
    k_fill<<<(NE + 255) / 256, 256>>>(esrc, edst);

    // ---- layer 1 (with ReLU) ----
    k_agg<true ><<<1184, 256>>>();   // users <- mean of item rows
    k_agg<false><<<1184, 256>>>();   // items <- mean of user rows
    k_transform<true,  true ><<<888, 256>>>(Wl1_iu, b1_iu, Wr1_iu);
    k_transform<true,  false><<<888, 256>>>(Wl1_ui, b1_ui, Wr1_ui);

    // ---- layer 2 (no ReLU) ----
    k_agg<true ><<<1184, 256>>>();
    k_agg<false><<<1184, 256>>>();
    k_transform<false, true ><<<888, 256>>>(Wl2_iu, b2_iu, Wr2_iu);
    k_transform<false, false><<<888, 256>>>(Wl2_ui, b2_ui, Wr2_ui);

    // ---- predictor ----
    k_dot<<<(NL * 8) / 256, 256>>>(lsrc, ldst, out);
}